// round 1
// baseline (speedup 1.0000x reference)
#include <cuda_runtime.h>

// EMA over time: out[b,0,c] = x[b,0,c]; out[b,t,c] = 0.1*x[b,t,c] + 0.9*out[b,t-1,c]
// Shape (16, 4096, 512) fp32.
//
// Exploit geometric decay: 0.9^128 ~ 1.4e-6, so a chunk of the scan can be
// reconstructed from a 128-step warmup window with error far below the 1e-3
// rel-err threshold. This parallelizes the serial scan into 16*8 chunk-scans.

namespace {
constexpr int T      = 4096;
constexpr int C      = 512;       // channels
constexpr int C4     = C / 4;     // float4 channel groups = 128
constexpr int CHUNK  = 512;       // timesteps per chunk
constexpr int NCHUNK = T / CHUNK; // 8
constexpr int W      = 128;       // warmup steps (decay 0.9^128 ~ 1.4e-6)
constexpr float A = 0.1f;
constexpr float B = 0.9f;
}

__global__ __launch_bounds__(C4) void ema_chunk_kernel(
    const float4* __restrict__ x, float4* __restrict__ out)
{
    const int c     = threadIdx.x;       // 0..127 float4 group
    const int chunk = blockIdx.x;        // 0..7
    const int b     = blockIdx.y;        // 0..15

    const size_t base = (size_t)b * T * C4 + c;
    const int t0 = chunk * CHUNK;

    float4 carry;

    if (chunk == 0) {
        // Exact start: out[0] = x[0]
        carry = x[base];
        out[base] = carry;
        const float4* xp = x + base;
        float4*       op = out + base;
        #pragma unroll 8
        for (int t = 1; t < CHUNK; ++t) {
            float4 v = xp[(size_t)t * C4];
            carry.x = fmaf(B, carry.x, A * v.x);
            carry.y = fmaf(B, carry.y, A * v.y);
            carry.z = fmaf(B, carry.z, A * v.z);
            carry.w = fmaf(B, carry.w, A * v.w);
            op[(size_t)t * C4] = carry;
        }
    } else {
        // Warmup: reconstruct carry from W steps before the chunk.
        const float4* wp = x + base + (size_t)(t0 - W) * C4;
        carry = wp[0];
        #pragma unroll 8
        for (int i = 1; i < W; ++i) {
            float4 v = wp[(size_t)i * C4];
            carry.x = fmaf(B, carry.x, A * v.x);
            carry.y = fmaf(B, carry.y, A * v.y);
            carry.z = fmaf(B, carry.z, A * v.z);
            carry.w = fmaf(B, carry.w, A * v.w);
        }
        // Main: compute and store this chunk.
        const float4* mp = x + base + (size_t)t0 * C4;
        float4*       op = out + base + (size_t)t0 * C4;
        #pragma unroll 8
        for (int t = 0; t < CHUNK; ++t) {
            float4 v = mp[(size_t)t * C4];
            carry.x = fmaf(B, carry.x, A * v.x);
            carry.y = fmaf(B, carry.y, A * v.y);
            carry.z = fmaf(B, carry.z, A * v.z);
            carry.w = fmaf(B, carry.w, A * v.w);
            op[(size_t)t * C4] = carry;
        }
    }
}

extern "C" void kernel_launch(void* const* d_in, const int* in_sizes, int n_in,
                              void* d_out, int out_size)
{
    const float4* x = (const float4*)d_in[0];
    float4* out = (float4*)d_out;
    dim3 grid(NCHUNK, 16);
    ema_chunk_kernel<<<grid, C4>>>(x, out);
}

// round 2
// speedup vs baseline: 1.6796x; 1.6796x over previous
#include <cuda_runtime.h>

// EMA over time: out[b,0,c] = x[b,0,c]; out[b,t,c] = 0.1*x[b,t,c] + 0.9*out[b,t-1,c]
// Shape (16, 4096, 512) fp32.
//
// Chunked scan with warmup truncation: 0.9^96 ~ 4e-5, so each chunk's carry is
// reconstructed from a 96-step warmup window (error ~1.5e-5 rel, threshold 1e-3).
// CHUNK=128 -> 32 chunks/batch -> 512 blocks (2048 warps) for latency hiding.

namespace {
constexpr int T      = 4096;
constexpr int C      = 512;       // channels
constexpr int C4     = C / 4;     // float4 channel groups = 128
constexpr int CHUNK  = 128;       // timesteps per chunk
constexpr int NCHUNK = T / CHUNK; // 32
constexpr int W      = 96;        // warmup steps (0.9^96 ~ 4e-5)
constexpr float A = 0.1f;
constexpr float B = 0.9f;
}

__global__ __launch_bounds__(C4) void ema_chunk_kernel(
    const float4* __restrict__ x, float4* __restrict__ out)
{
    const int c     = threadIdx.x;       // 0..127 float4 group
    const int chunk = blockIdx.x;        // 0..31
    const int b     = blockIdx.y;        // 0..15

    const size_t base = (size_t)b * T * C4 + c;
    const int t0 = chunk * CHUNK;

    float4 carry;

    if (chunk == 0) {
        // Exact start: out[0] = x[0]
        carry = x[base];
        out[base] = carry;
        const float4* xp = x + base;
        float4*       op = out + base;
        #pragma unroll 8
        for (int t = 1; t < CHUNK; ++t) {
            float4 v = xp[(size_t)t * C4];
            carry.x = fmaf(B, carry.x, A * v.x);
            carry.y = fmaf(B, carry.y, A * v.y);
            carry.z = fmaf(B, carry.z, A * v.z);
            carry.w = fmaf(B, carry.w, A * v.w);
            op[(size_t)t * C4] = carry;
        }
    } else {
        // Warmup: reconstruct carry from W steps before the chunk.
        const float4* wp = x + base + (size_t)(t0 - W) * C4;
        carry = wp[0];
        #pragma unroll 8
        for (int i = 1; i < W; ++i) {
            float4 v = wp[(size_t)i * C4];
            carry.x = fmaf(B, carry.x, A * v.x);
            carry.y = fmaf(B, carry.y, A * v.y);
            carry.z = fmaf(B, carry.z, A * v.z);
            carry.w = fmaf(B, carry.w, A * v.w);
        }
        // Main: compute and store this chunk.
        const float4* mp = x + base + (size_t)t0 * C4;
        float4*       op = out + base + (size_t)t0 * C4;
        #pragma unroll 8
        for (int t = 0; t < CHUNK; ++t) {
            float4 v = mp[(size_t)t * C4];
            carry.x = fmaf(B, carry.x, A * v.x);
            carry.y = fmaf(B, carry.y, A * v.y);
            carry.z = fmaf(B, carry.z, A * v.z);
            carry.w = fmaf(B, carry.w, A * v.w);
            op[(size_t)t * C4] = carry;
        }
    }
}

extern "C" void kernel_launch(void* const* d_in, const int* in_sizes, int n_in,
                              void* d_out, int out_size)
{
    const float4* x = (const float4*)d_in[0];
    float4* out = (float4*)d_out;
    dim3 grid(NCHUNK, 16);
    ema_chunk_kernel<<<grid, C4>>>(x, out);
}